// round 8
// baseline (speedup 1.0000x reference)
#include <cuda_runtime.h>
#include <cuda_bf16.h>
#include <cstdint>

// ---------------------------------------------------------------------------
// GASP_EGNN coordinate update on GB300 (sm_103a) — round 7: mma.sync bf16, M=32
// out = coord + segment_sum( (coord[r]-coord[c])/(||.||+1) * MLP(h[r],h[c],ea), r)/100
//
// R7: 32 edges per warp-tile — every B-fragment LDS.64 feeds TWO m16n8k16
// HMMAs (rows 0-15 / 16-31), halving B smem traffic per edge (L1 was 80%).
// 384 thr/CTA (12 warps) for register headroom; all 32 lanes own an edge in
// the epilogue. Layer1 D-frags -> SiLU -> layer2 A-frags stay in registers.
// ---------------------------------------------------------------------------

#define HID   64
#define EIN   8
#define EPW   32
#define XSTRIDE 304                 // bytes per X row; 16*19 -> ldmatrix clean
#define XBYTES  (EPW * XSTRIDE)     // 9728 B per warp
#define NWARPS  12
#define NTHREADS (NWARPS * 32)
#define NT1   9                     // layer1 k-tiles (K=144)
#define NT2   5                     // layer2 k-tiles (K=80)

typedef uint32_t u32;
typedef unsigned long long ull;

__device__ __forceinline__ u32 smem_u32(const void* p) {
    u32 a;
    asm("{ .reg .u64 t; cvta.to.shared.u64 t, %1; cvt.u32.u64 %0, t; }"
        : "=r"(a) : "l"(p));
    return a;
}
__device__ __forceinline__ u32 cvt2(float a, float b) {
    __nv_bfloat162 t = __floats2bfloat162_rn(a, b);
    return *(u32*)&t;
}
__device__ __forceinline__ float silu1(float x) {
    float t;
    asm("tanh.approx.f32 %0, %1;" : "=f"(t) : "f"(0.5f * x));
    return 0.5f * x * (1.0f + t);
}
__device__ __forceinline__ void ldsm4(u32& r0, u32& r1, u32& r2, u32& r3, u32 addr) {
    asm volatile("ldmatrix.sync.aligned.m8n8.x4.shared.b16 {%0,%1,%2,%3}, [%4];"
                 : "=r"(r0), "=r"(r1), "=r"(r2), "=r"(r3) : "r"(addr));
}
__device__ __forceinline__ void mma16816(float* d, u32 a0, u32 a1, u32 a2, u32 a3,
                                         u32 b0, u32 b1) {
    asm volatile("mma.sync.aligned.m16n8k16.row.col.f32.bf16.bf16.f32 "
                 "{%0,%1,%2,%3}, {%4,%5,%6,%7}, {%8,%9}, {%0,%1,%2,%3};"
                 : "+f"(d[0]), "+f"(d[1]), "+f"(d[2]), "+f"(d[3])
                 : "r"(a0), "r"(a1), "r"(a2), "r"(a3), "r"(b0), "r"(b1));
}

__global__ void egnn_init_out(const float* __restrict__ coord, float* __restrict__ out, int n) {
    int i = blockIdx.x * blockDim.x + threadIdx.x;
    if (i < n) out[i] = coord[i];
}

// smem bytes: sB1f 18432 | sB2f 10240 | sW3 256 | X stages 12*9728 = 116736
#define SB1_OFF  0
#define SB2_OFF  18432
#define SW3_OFF  (18432 + 10240)
#define SX_OFF   (SW3_OFF + 256)
#define SMEM_BYTES (SX_OFF + NWARPS * XBYTES)

__global__ __launch_bounds__(NTHREADS, 1)
void egnn_mma_kernel(
    const float* __restrict__ h, const float* __restrict__ coord,
    const int*   __restrict__ ei, const float* __restrict__ ea,
    const float* __restrict__ W1, const float* __restrict__ b1,
    const float* __restrict__ W2, const float* __restrict__ b2,
    const float* __restrict__ W3, float* __restrict__ out, int E)
{
    extern __shared__ char sm[];
    uint2* sB1f = (uint2*)(sm + SB1_OFF);   // [t][j][lane] -> (breg0, breg1)
    uint2* sB2f = (uint2*)(sm + SB2_OFF);
    float* sW3  = (float*)(sm + SW3_OFF);

    const int tid  = threadIdx.x;
    const int lane = tid & 31;
    const int wid  = tid >> 5;
    char* sXw = sm + SX_OFF + wid * XBYTES;     // this warp's X stage [32][304B]

    // ---- precompute B fragments for W1 (K=144: row 136=b1, 137..143=0) -----
    for (int idx = tid; idx < NT1 * 8 * 32; idx += NTHREADS) {
        int t = idx >> 8, j = (idx >> 5) & 7, l = idx & 31;
        int n  = j * 8 + (l >> 2);
        int k0 = t * 16 + (l & 3) * 2;
        float v0 = (k0     < 136) ? W1[k0 * HID + n]       : ((k0     == 136) ? b1[n] : 0.0f);
        float v1 = (k0 + 1 < 136) ? W1[(k0 + 1) * HID + n] : ((k0 + 1 == 136) ? b1[n] : 0.0f);
        int k1 = k0 + 8;
        float v2 = (k1     < 136) ? W1[k1 * HID + n]       : ((k1     == 136) ? b1[n] : 0.0f);
        float v3 = (k1 + 1 < 136) ? W1[(k1 + 1) * HID + n] : ((k1 + 1 == 136) ? b1[n] : 0.0f);
        sB1f[idx] = make_uint2(cvt2(v0, v1), cvt2(v2, v3));
    }
    // ---- precompute B fragments for W2 (K=80: row 64=b2, 65..79=0) ---------
    for (int idx = tid; idx < NT2 * 8 * 32; idx += NTHREADS) {
        int t = idx >> 8, j = (idx >> 5) & 7, l = idx & 31;
        int n  = j * 8 + (l >> 2);
        int k0 = t * 16 + (l & 3) * 2;
        float v0 = (k0     < 64) ? W2[k0 * HID + n]       : ((k0     == 64) ? b2[n] : 0.0f);
        float v1 = (k0 + 1 < 64) ? W2[(k0 + 1) * HID + n] : ((k0 + 1 == 64) ? b2[n] : 0.0f);
        int k1 = k0 + 8;
        float v2 = (k1     < 64) ? W2[k1 * HID + n]       : ((k1     == 64) ? b2[n] : 0.0f);
        float v3 = (k1 + 1 < 64) ? W2[(k1 + 1) * HID + n] : ((k1 + 1 == 64) ? b2[n] : 0.0f);
        sB2f[idx] = make_uint2(cvt2(v0, v1), cvt2(v2, v3));
    }
    if (tid < HID) sW3[tid] = W3[tid];

    // ---- X pad cols: col136=1 (layer1 bias), 137..143=0 (write once) -------
    {
        *(ull*)(sXw + lane * XSTRIDE + 272) = 0x3F80ULL;   // bf16(1.0),0,0,0
        *(ull*)(sXw + lane * XSTRIDE + 280) = 0ULL;
    }
    __syncthreads();

    const unsigned FULL = 0xffffffffu;
    const int nwarps  = gridDim.x * NWARPS;
    const int gwid    = blockIdx.x * NWARPS + wid;
    const int ngroups = E / EPW;

    const u32 lm_lo = smem_u32(sXw) + (u32)(lane & 15) * XSTRIDE
                      + ((lane & 16) ? 16u : 0u);
    const u32 lm_hi = lm_lo + 16 * XSTRIDE;
    const int l4 = lane & 3;
    const u32 bias_a = (l4 == 0) ? cvt2(1.0f, 0.0f) : 0u;  // layer2 bias A-frag

    // hoist W3 into registers (per-lane cols j*8 + l4*2, +1)
    float w3r0[8], w3r1[8];
    #pragma unroll
    for (int j = 0; j < 8; j++) {
        w3r0[j] = sW3[j * 8 + l4 * 2];
        w3r1[j] = sW3[j * 8 + l4 * 2 + 1];
    }

    for (int g = gwid; g < ngroups; g += nwarps) {
        const int ebase = g * EPW;

        const int t_r = ei[ebase + lane];        // rn for edge `lane`
        const int t_c = ei[E + ebase + lane];    // cn for edge `lane`

        // ================= stage X (bf16) ==================================
        {
            const int sel     = lane >> 3;        // 0..3
            const int nodesel = sel >> 1;         // 0=rn 1=cn
            const int half    = sel & 1;
            const int qi      = lane & 7;
            #pragma unroll
            for (int i = 0; i < EPW; i++) {
                int nr = __shfl_sync(FULL, t_r, i);
                int nc = __shfl_sync(FULL, t_c, i);
                int node = nodesel ? nc : nr;
                float4 v = *(const float4*)(h + (size_t)node * HID + half * 32 + qi * 4);
                *(uint2*)(sXw + i * XSTRIDE + nodesel * 128 + half * 64 + qi * 8)
                    = make_uint2(cvt2(v.x, v.y), cvt2(v.z, v.w));
            }
            // edge_attr: 32 edges x 8 floats
            #pragma unroll
            for (int r = 0; r < 2; r++) {
                int idx = lane + 32 * r;
                float4 va = *(const float4*)(ea + (size_t)ebase * EIN + idx * 4);
                *(uint2*)(sXw + (idx >> 1) * XSTRIDE + 256 + (idx & 1) * 8)
                    = make_uint2(cvt2(va.x, va.y), cvt2(va.z, va.w));
            }
        }
        __syncwarp();

        // ================= layer 1: 9 k-tiles x 8 n x 2 m ==================
        float dlo[8][4], dhi[8][4];
        #pragma unroll
        for (int j = 0; j < 8; j++)
            #pragma unroll
            for (int q = 0; q < 4; q++) { dlo[j][q] = 0.0f; dhi[j][q] = 0.0f; }

        #pragma unroll
        for (int tt = 0; tt < NT1; tt++) {
            u32 a0, a1, a2, a3, c0, c1, c2, c3;
            ldsm4(a0, a1, a2, a3, lm_lo + tt * 32);
            ldsm4(c0, c1, c2, c3, lm_hi + tt * 32);
            #pragma unroll
            for (int j = 0; j < 8; j++) {
                uint2 b = sB1f[(tt * 8 + j) * 32 + lane];
                mma16816(dlo[j], a0, a1, a2, a3, b.x, b.y);
                mma16816(dhi[j], c0, c1, c2, c3, b.x, b.y);
            }
        }
        __syncwarp();

        // ===== SiLU(D1) -> layer2 A-fragments, in registers ================
        u32 a2lo[NT2][4], a2hi[NT2][4];
        #pragma unroll
        for (int j = 0; j < 8; j++) {
            int t2 = j >> 1, hf = (j & 1) * 2;
            a2lo[t2][hf + 0] = cvt2(silu1(dlo[j][0]), silu1(dlo[j][1]));
            a2lo[t2][hf + 1] = cvt2(silu1(dlo[j][2]), silu1(dlo[j][3]));
            a2hi[t2][hf + 0] = cvt2(silu1(dhi[j][0]), silu1(dhi[j][1]));
            a2hi[t2][hf + 1] = cvt2(silu1(dhi[j][2]), silu1(dhi[j][3]));
        }
        a2lo[4][0] = bias_a; a2lo[4][1] = bias_a; a2lo[4][2] = 0; a2lo[4][3] = 0;
        a2hi[4][0] = bias_a; a2hi[4][1] = bias_a; a2hi[4][2] = 0; a2hi[4][3] = 0;

        // ================= layer 2: 5 k-tiles x 8 n x 2 m ==================
        float elo[8][4], ehi[8][4];
        #pragma unroll
        for (int j = 0; j < 8; j++)
            #pragma unroll
            for (int q = 0; q < 4; q++) { elo[j][q] = 0.0f; ehi[j][q] = 0.0f; }

        #pragma unroll
        for (int tt = 0; tt < NT2; tt++) {
            #pragma unroll
            for (int j = 0; j < 8; j++) {
                uint2 b = sB2f[(tt * 8 + j) * 32 + lane];
                mma16816(elo[j], a2lo[tt][0], a2lo[tt][1], a2lo[tt][2], a2lo[tt][3],
                         b.x, b.y);
                mma16816(ehi[j], a2hi[tt][0], a2hi[tt][1], a2hi[tt][2], a2hi[tt][3],
                         b.x, b.y);
            }
        }

        // ===== SiLU(D2) . W3, quad reduce ==================================
        float s00 = 0.0f, s01 = 0.0f, s10 = 0.0f, s11 = 0.0f;
        #pragma unroll
        for (int j = 0; j < 8; j++) {
            float w0 = w3r0[j], w1 = w3r1[j];
            s00 += silu1(elo[j][0]) * w0 + silu1(elo[j][1]) * w1;
            s01 += silu1(elo[j][2]) * w0 + silu1(elo[j][3]) * w1;
            s10 += silu1(ehi[j][0]) * w0 + silu1(ehi[j][1]) * w1;
            s11 += silu1(ehi[j][2]) * w0 + silu1(ehi[j][3]) * w1;
        }
        #pragma unroll
        for (int off = 1; off <= 2; off <<= 1) {
            s00 += __shfl_xor_sync(FULL, s00, off);
            s01 += __shfl_xor_sync(FULL, s01, off);
            s10 += __shfl_xor_sync(FULL, s10, off);
            s11 += __shfl_xor_sync(FULL, s11, off);
        }

        // ===== epilogue: lane e owns edge e (all 32 lanes) =================
        const u32 src = (u32)((lane & 7) * 4);
        float v0 = __shfl_sync(FULL, s00, src);
        float v1 = __shfl_sync(FULL, s01, src);
        float v2 = __shfl_sync(FULL, s10, src);
        float v3 = __shfl_sync(FULL, s11, src);
        const int qd = lane >> 3;
        const float sc = (qd == 0) ? v0 : (qd == 1) ? v1 : (qd == 2) ? v2 : v3;

        const float dx = coord[t_r * 3 + 0] - coord[t_c * 3 + 0];
        const float dy = coord[t_r * 3 + 1] - coord[t_c * 3 + 1];
        const float dz = coord[t_r * 3 + 2] - coord[t_c * 3 + 2];
        const float nrm = sqrtf(dx * dx + dy * dy + dz * dz + 1e-8f);
        const float f = sc / ((nrm + 1.0f) * 100.0f);
        atomicAdd(&out[t_r * 3 + 0], dx * f);
        atomicAdd(&out[t_r * 3 + 1], dy * f);
        atomicAdd(&out[t_r * 3 + 2], dz * f);
        __syncwarp();
    }
}

extern "C" void kernel_launch(void* const* d_in, const int* in_sizes, int n_in,
                              void* d_out, int out_size)
{
    const float* h     = (const float*)d_in[0];
    const float* coord = (const float*)d_in[1];
    const int*   ei    = (const int*)  d_in[2];
    const float* ea    = (const float*)d_in[3];
    const float* W1    = (const float*)d_in[4];
    const float* b1    = (const float*)d_in[5];
    const float* W2    = (const float*)d_in[6];
    const float* b2    = (const float*)d_in[7];
    const float* W3    = (const float*)d_in[8];
    float* out = (float*)d_out;

    const int E = in_sizes[3] / EIN;   // 1,600,000 (divisible by 32)

    egnn_init_out<<<(out_size + 255) / 256, 256>>>(coord, out, out_size);

    cudaFuncSetAttribute(egnn_mma_kernel,
                         cudaFuncAttributeMaxDynamicSharedMemorySize, SMEM_BYTES);
    egnn_mma_kernel<<<148, NTHREADS, SMEM_BYTES>>>(h, coord, ei, ea,
                                                   W1, b1, W2, b2, W3, out, E);
}